// round 1
// baseline (speedup 1.0000x reference)
#include <cuda_runtime.h>
#include <cstdint>

// feats[n,f] = sum_{p,q} k0[n,p] * IF[f,p,q] * k1[n,q]
//   = GEMM:  O[n, f] = W[n, pq] @ B[pq, f],  W[n, p*28+q] = k0[n,p]*k1[n,q]
// W generated on the fly from per-point exp() values held in smem.
// Packed fp32 (fma.rn.f32x2) pairs along the point dimension.

#define PP 28
#define TM 128   // points per CTA
#define TF 128   // features (= F)
#define NTHREADS 256

#define MUL2(d, a, b) asm("mul.rn.f32x2 %0, %1, %2;" : "=l"(d) : "l"(a), "l"(b))
#define FMA2(d, a, b) asm("fma.rn.f32x2 %0, %1, %2, %0;" : "+l"(d) : "l"(a), "l"(b))
#define PACK2(d, s)   asm("mov.b64 %0, {%1, %1};" : "=l"(d) : "r"(s))

__global__ __launch_bounds__(NTHREADS, 2)
void image_features_map_kernel(const float* __restrict__ x,
                               const float* __restrict__ sigma,
                               const float* __restrict__ IF,
                               float* __restrict__ out)
{
    __shared__ float k0s[PP][TM];   // 14 KB  k0s[p][m]
    __shared__ float k1s[PP][TM];   // 14 KB  k1s[q][m]
    __shared__ float bs[PP][TF];    // 14 KB  bs[q][f] = IF[f, p, q] for current p
    __shared__ float xs[TM * 2];    //  1 KB

    const int tid = threadIdx.x;
    const int m0  = blockIdx.x * TM;

    // ---- stage x coords for this tile (256 floats, one per thread) ----
    xs[tid] = x[m0 * 2 + tid];
    __syncthreads();

    const float ls  = __expf(sigma[0]);
    const float inv = 0.5f / (ls * ls);

    // ---- compute Gaussian kernel vectors k0, k1 for all 128 points ----
    for (int t = tid; t < PP * TM; t += NTHREADS) {
        const int p = t >> 7;       // 0..27
        const int m = t & 127;      // 0..127
        const float g  = 0.001f + (float)p * (0.998f / 27.0f);
        const float d0 = g - xs[2 * m + 0];
        const float d1 = g - xs[2 * m + 1];
        k0s[p][m] = __expf(-inv * d0 * d0);
        k1s[p][m] = __expf(-inv * d1 * d1);
    }

    // ---- accumulators: 8 m-rows (as 4 f32x2 pairs) x 8 f-cols ----
    unsigned long long acc[4][8];
    #pragma unroll
    for (int i = 0; i < 4; i++)
        #pragma unroll
        for (int j = 0; j < 8; j++) acc[i][j] = 0ull;

    const int tm    = tid >> 4;     // 0..15
    const int tf    = tid & 15;     // 0..15
    const int mBase = tm * 8;
    const int fBase = tf * 8;

    for (int p = 0; p < PP; p++) {
        // ---- stage B tile: bs[q][f] = IF[f*784 + p*28 + q] ----
        __syncthreads();   // (also covers k0s/k1s readiness on first iter)
        for (int idx = tid; idx < TF * 7; idx += NTHREADS) {
            const int f = idx / 7;
            const int v = idx - f * 7;           // which float4 along q
            const float4 d = *reinterpret_cast<const float4*>(
                IF + f * (PP * PP) + p * PP + v * 4);
            bs[v * 4 + 0][f] = d.x;
            bs[v * 4 + 1][f] = d.y;
            bs[v * 4 + 2][f] = d.z;
            bs[v * 4 + 3][f] = d.w;
        }
        __syncthreads();

        // ---- k0 fragment for this p (4 packed pairs = 8 points) ----
        const ulonglong2 k0a = *reinterpret_cast<const ulonglong2*>(&k0s[p][mBase]);
        const ulonglong2 k0b = *reinterpret_cast<const ulonglong2*>(&k0s[p][mBase + 4]);
        const unsigned long long k0p0 = k0a.x, k0p1 = k0a.y;
        const unsigned long long k0p2 = k0b.x, k0p3 = k0b.y;

        #pragma unroll 4
        for (int q = 0; q < PP; q++) {
            const ulonglong2 k1a = *reinterpret_cast<const ulonglong2*>(&k1s[q][mBase]);
            const ulonglong2 k1b = *reinterpret_cast<const ulonglong2*>(&k1s[q][mBase + 4]);
            unsigned long long t0, t1, t2, t3;
            MUL2(t0, k0p0, k1a.x);              // t[m] = k0[m][p] * k1[m][q]
            MUL2(t1, k0p1, k1a.y);
            MUL2(t2, k0p2, k1b.x);
            MUL2(t3, k0p3, k1b.y);

            const float4 ba = *reinterpret_cast<const float4*>(&bs[q][fBase]);
            const float4 bb = *reinterpret_cast<const float4*>(&bs[q][fBase + 4]);
            const float bf[8] = {ba.x, ba.y, ba.z, ba.w, bb.x, bb.y, bb.z, bb.w};

            #pragma unroll
            for (int j = 0; j < 8; j++) {
                unsigned long long bd;
                PACK2(bd, __float_as_uint(bf[j]));
                FMA2(acc[0][j], t0, bd);
                FMA2(acc[1][j], t1, bd);
                FMA2(acc[2][j], t2, bd);
                FMA2(acc[3][j], t3, bd);
            }
        }
    }

    // ---- epilogue: acc[ip][j] -> rows (mBase+2ip, +1), col fBase+j ----
    #pragma unroll
    for (int ip = 0; ip < 4; ip++) {
        float2 v[8];
        #pragma unroll
        for (int j = 0; j < 8; j++)
            v[j] = *reinterpret_cast<float2*>(&acc[ip][j]);

        float* o = out + (size_t)(m0 + mBase + 2 * ip) * TF + fBase;
        const float4 lo0 = make_float4(v[0].x, v[1].x, v[2].x, v[3].x);
        const float4 lo1 = make_float4(v[4].x, v[5].x, v[6].x, v[7].x);
        const float4 hi0 = make_float4(v[0].y, v[1].y, v[2].y, v[3].y);
        const float4 hi1 = make_float4(v[4].y, v[5].y, v[6].y, v[7].y);
        *reinterpret_cast<float4*>(o)          = lo0;
        *reinterpret_cast<float4*>(o + 4)      = lo1;
        *reinterpret_cast<float4*>(o + TF)     = hi0;
        *reinterpret_cast<float4*>(o + TF + 4) = hi1;
    }
}

extern "C" void kernel_launch(void* const* d_in, const int* in_sizes, int n_in,
                              void* d_out, int out_size)
{
    const float* x     = (const float*)d_in[0];   // [B, N, 2]
    const float* sigma = (const float*)d_in[1];   // [1]
    const float* IF    = (const float*)d_in[2];   // [F, P, P]
    float* out         = (float*)d_out;           // [B, N, F]

    const int npoints = in_sizes[0] / 2;          // B*N = 131072
    const int nblocks = npoints / TM;             // 1024

    image_features_map_kernel<<<nblocks, NTHREADS>>>(x, sigma, IF, out);
}

// round 4
// speedup vs baseline: 1.7707x; 1.7707x over previous
#include <cuda_runtime.h>
#include <cuda_fp16.h>
#include <cstdint>

// feats[n,f] = sum_{pq} W[n,pq] * IF[f,pq],  W[n, p*28+q] = k0[n,p]*k1[n,q]
// Classic mma.sync (m16n8k16 f16->f32) GEMM, 3-pass hi/lo split precision:
//   D = Ah*Bh + Al*Bh + Ah*Bl   (residual ~2^-24)
// K = 784 = 49*16 exactly; chunked as 7 chunks of 112 (4 p-values each).
// A built on the fly in smem from exp tables; B pre-split to fp16 hi/lo by a
// prep kernel in the exact smem image (240B row stride -> odd 16B-unit stride
// -> conflict-free ldmatrix), streamed with cp.async.cg double buffering.
// Both A and B are K-major [row][k] -> both use NON-transposed ldmatrix.

#define PP 28
#define CHUNKS 7
#define KSTEP 7              // k16 steps per chunk (112/16)
#define TM 128
#define TF 128
#define NTHREADS 256
#define ROWB 240             // smem row stride bytes (120 fp16, 112 used)
#define TEN_BYTES 30720      // one tensor: 128 rows * 240B
#define CH_BYTES 61440       // hi + lo per chunk

// smem offsets (bytes)
#define OFF_A   0            // Ahi [0,30720) Alo [30720,61440)
#define OFF_B0  61440
#define OFF_B1  122880
#define OFF_K0  184320       // k0s[28][128] float
#define OFF_K1  198656       // k1s[28][128] float
#define OFF_XS  212992       // xs[256] float
#define SMEM_TOT 214016

static __device__ __align__(16) unsigned char g_B[CHUNKS * CH_BYTES];

__device__ __forceinline__ uint32_t smem_u32(const void* p) {
    uint32_t a;
    asm("{ .reg .u64 t; cvta.to.shared.u64 t, %1; cvt.u32.u64 %0, t; }" : "=r"(a) : "l"(p));
    return a;
}

#define LDSM4(r0, r1, r2, r3, a)                                               \
    asm volatile("ldmatrix.sync.aligned.m8n8.x4.shared.b16 {%0,%1,%2,%3}, [%4];" \
                 : "=r"(r0), "=r"(r1), "=r"(r2), "=r"(r3) : "r"(a))
#define MMA16816(d, a, b0, b1)                                                 \
    asm volatile("mma.sync.aligned.m16n8k16.row.col.f32.f16.f16.f32 "          \
                 "{%0,%1,%2,%3}, {%4,%5,%6,%7}, {%8,%9}, {%0,%1,%2,%3};"       \
                 : "+f"((d)[0]), "+f"((d)[1]), "+f"((d)[2]), "+f"((d)[3])      \
                 : "r"((a)[0]), "r"((a)[1]), "r"((a)[2]), "r"((a)[3]),         \
                   "r"(b0), "r"(b1))
#define CPASYNC16(dst, src)                                                    \
    asm volatile("cp.async.cg.shared.global [%0], [%1], 16;" :: "r"(dst), "l"(src))

// ---------------- prep: split IF into fp16 hi/lo chunk images ----------------
__global__ void prep_kernel(const float* __restrict__ IF) {
    int idx = blockIdx.x * 256 + threadIdx.x;
    if (idx >= CHUNKS * TF * 56) return;
    const int c  = idx / (TF * 56);
    const int r  = idx - c * (TF * 56);
    const int f  = r / 56;
    const int i  = r - f * 56;
    const int kk = 2 * i;                // local k within chunk, even
    const int pl = kk / PP;              // 0..3
    const int q  = kk - pl * PP;         // even, q+1 <= 27
    const int p  = c * 4 + pl;
    const float v0 = IF[f * (PP * PP) + p * PP + q];
    const float v1 = IF[f * (PP * PP) + p * PP + q + 1];
    __half2 hi = __floats2half2_rn(v0, v1);
    float2 hf  = __half22float2(hi);
    __half2 lo = __floats2half2_rn(v0 - hf.x, v1 - hf.y);
    unsigned char* base = g_B + (size_t)c * CH_BYTES + f * ROWB + kk * 2;
    *reinterpret_cast<uint32_t*>(base)             = *reinterpret_cast<uint32_t*>(&hi);
    *reinterpret_cast<uint32_t*>(base + TEN_BYTES) = *reinterpret_cast<uint32_t*>(&lo);
}

// ---------------- main kernel ----------------
__global__ __launch_bounds__(NTHREADS, 1)
void image_features_hmma_kernel(const float* __restrict__ x,
                                const float* __restrict__ sigma,
                                float* __restrict__ out)
{
    extern __shared__ unsigned char smem[];
    const uint32_t sb = smem_u32(smem);

    const int tid  = threadIdx.x;
    const int lane = tid & 31;
    const int w    = tid >> 5;
    const int wm   = w >> 2;     // 0..1 : rows [wm*64, +64)
    const int wn   = w & 3;      // 0..3 : cols [wn*32, +32)
    const int m0   = blockIdx.x * TM;

    float* xs  = reinterpret_cast<float*>(smem + OFF_XS);
    float* k0s = reinterpret_cast<float*>(smem + OFF_K0);
    float* k1s = reinterpret_cast<float*>(smem + OFF_K1);

    xs[tid] = x[m0 * 2 + tid];
    __syncthreads();

    const float ls  = __expf(sigma[0]);
    const float inv = 0.5f / (ls * ls);

    // exp tables, layout [grid_idx][m] -> conflict-free reads in A-build
    for (int idx = tid; idx < PP * TM; idx += NTHREADS) {
        const int g = idx >> 7;
        const int m = idx & 127;
        const float gv = 0.001f + (float)g * (0.998f / 27.0f);
        const float d0 = gv - xs[2 * m + 0];
        const float d1 = gv - xs[2 * m + 1];
        k0s[g * 128 + m] = __expf(-inv * d0 * d0);
        k1s[g * 128 + m] = __expf(-inv * d1 * d1);
    }
    __syncthreads();

    // ---- B prefetch (cp.async.cg, 240B per thread per chunk) ----
    auto prefetch = [&](int c, int buf) {
        uint32_t dst = sb + (buf ? OFF_B1 : OFF_B0) + tid * ROWB;
        const unsigned char* src = g_B + (size_t)c * CH_BYTES + tid * ROWB;
        #pragma unroll
        for (int j = 0; j < 15; j++) CPASYNC16(dst + 16 * j, src + 16 * j);
        asm volatile("cp.async.commit_group;" ::: "memory");
    };
    prefetch(0, 0);

    float acc[4][4][4];
    #pragma unroll
    for (int i = 0; i < 4; i++)
        #pragma unroll
        for (int j = 0; j < 4; j++)
            #pragma unroll
            for (int k = 0; k < 4; k++) acc[i][j][k] = 0.0f;

    const int m_ = tid >> 1;     // A-build row
    const int h_ = tid & 1;      // which 56-wide half of the 112 chunk-K

    for (int c = 0; c < CHUNKS; c++) {
        if (c + 1 < CHUNKS) prefetch(c + 1, (c + 1) & 1);

        // ---- build A chunk: A[m][kk] = k0[m, 4c + kk/28] * k1[m, kk%28] ----
        {
            unsigned char* Ab = smem + OFF_A;
            #pragma unroll
            for (int sub = 0; sub < 2; sub++) {
                const int p = 4 * c + 2 * h_ + sub;
                const float k0v = k0s[p * 128 + m_];
                #pragma unroll
                for (int i2 = 0; i2 < 14; i2++) {
                    const int q = 2 * i2;
                    const float pr0 = k0v * k1s[q * 128 + m_];
                    const float pr1 = k0v * k1s[(q + 1) * 128 + m_];
                    __half2 hi = __floats2half2_rn(pr0, pr1);
                    float2 hf  = __half22float2(hi);
                    __half2 lo = __floats2half2_rn(pr0 - hf.x, pr1 - hf.y);
                    const int kk  = (2 * h_ + sub) * PP + q;
                    const int off = m_ * ROWB + kk * 2;
                    *reinterpret_cast<uint32_t*>(Ab + off) =
                        *reinterpret_cast<uint32_t*>(&hi);
                    *reinterpret_cast<uint32_t*>(Ab + TEN_BYTES + off) =
                        *reinterpret_cast<uint32_t*>(&lo);
                }
            }
        }

        if (c + 1 < CHUNKS) asm volatile("cp.async.wait_group %0;" :: "n"(1) : "memory");
        else                asm volatile("cp.async.wait_group %0;" :: "n"(0) : "memory");
        __syncthreads();

        const uint32_t sAh = sb + OFF_A;
        const uint32_t sB  = sb + ((c & 1) ? OFF_B1 : OFF_B0);

        // per-lane ldmatrix address components (rows 0-15, +16B for hi lanes)
        const uint32_t aoff = (lane & 15) * ROWB + (((lane >> 4) << 3) * 2);

        for (int s = 0; s < KSTEP; s++) {
            const uint32_t kboff = s * 32;   // s*16 halfs * 2B

            uint32_t ah[4][4], al[4][4];
            #pragma unroll
            for (int i = 0; i < 4; i++) {
                const uint32_t aa = sAh + (wm * 64 + i * 16) * ROWB + aoff + kboff;
                LDSM4(ah[i][0], ah[i][1], ah[i][2], ah[i][3], aa);
                LDSM4(al[i][0], al[i][1], al[i][2], al[i][3], aa + TEN_BYTES);
            }

            uint32_t bh[2][4], bl[2][4];
            #pragma unroll
            for (int g = 0; g < 2; g++) {
                const uint32_t ba = sB + (wn * 32 + g * 16) * ROWB + aoff + kboff;
                LDSM4(bh[g][0], bh[g][1], bh[g][2], bh[g][3], ba);
                LDSM4(bl[g][0], bl[g][1], bl[g][2], bl[g][3], ba + TEN_BYTES);
            }

            #pragma unroll
            for (int i = 0; i < 4; i++)
                #pragma unroll
                for (int j = 0; j < 4; j++) {
                    const int jg = j >> 1, par = j & 1;
                    MMA16816(acc[i][j], ah[i], bh[jg][par], bh[jg][par + 2]);
                    MMA16816(acc[i][j], al[i], bh[jg][par], bh[jg][par + 2]);
                    MMA16816(acc[i][j], ah[i], bl[jg][par], bl[jg][par + 2]);
                }
        }
        __syncthreads();   // before next chunk's A-build overwrites A
    }

    // ---- epilogue: direct STG, float2 per acc-pair ----
    float* op = out + (size_t)(m0 + wm * 64) * TF + wn * 32;
    #pragma unroll
    for (int i = 0; i < 4; i++) {
        const int row = i * 16 + (lane >> 2);
        #pragma unroll
        for (int j = 0; j < 4; j++) {
            const int col = j * 8 + 2 * (lane & 3);
            float2 v0 = make_float2(acc[i][j][0], acc[i][j][1]);
            float2 v1 = make_float2(acc[i][j][2], acc[i][j][3]);
            *reinterpret_cast<float2*>(op + (size_t)row * TF + col)       = v0;
            *reinterpret_cast<float2*>(op + (size_t)(row + 8) * TF + col) = v1;
        }
    }
}

extern "C" void kernel_launch(void* const* d_in, const int* in_sizes, int n_in,
                              void* d_out, int out_size)
{
    const float* x     = (const float*)d_in[0];   // [B, N, 2]
    const float* sigma = (const float*)d_in[1];   // [1]
    const float* IF    = (const float*)d_in[2];   // [F, P, P]
    float* out         = (float*)d_out;           // [B*N, F]

    const int npoints = in_sizes[0] / 2;
    const int nblocks = npoints / TM;             // 1024

    static bool attr_set = false;
    if (!attr_set) {
        cudaFuncSetAttribute(image_features_hmma_kernel,
                             cudaFuncAttributeMaxDynamicSharedMemorySize, SMEM_TOT);
        attr_set = true;
    }

    const int prep_n = CHUNKS * TF * 56;
    prep_kernel<<<(prep_n + 255) / 256, 256>>>(IF);
    image_features_hmma_kernel<<<nblocks, NTHREADS, SMEM_TOT>>>(x, sigma, out);
}

// round 5
// speedup vs baseline: 2.4146x; 1.3636x over previous
#include <cuda_runtime.h>
#include <cuda_fp16.h>
#include <cstdint>

// feats[n,f] = sum_{pq} W[n,pq] * IF[f,pq],  W[n, p*28+q] = k0[n,p]*k1[n,q]
// mma.sync m16n8k16 f16->f32 GEMM, 3-pass hi/lo split: D = Ah*Bh + Al*Bh + Ah*Bl.
// Round 5: 512 threads / 16 warps (4x4 warp grid, 32x32 output each) to lift
// occupancy/issue (was 8 warps, tensor pipe 38% busy).

#define PP 28
#define CHUNKS 7
#define KSTEP 7              // k16 steps per chunk (112/16)
#define TM 128
#define TF 128
#define NTHREADS 512
#define ROWB 240             // smem row stride bytes (120 fp16, 112 used; odd 16B units)
#define TEN_BYTES 30720      // one tensor: 128 rows * 240B
#define CH_BYTES 61440       // hi + lo per chunk

// smem offsets (bytes)
#define OFF_A   0            // Ahi [0,30720) Alo [30720,61440)
#define OFF_B0  61440
#define OFF_B1  122880
#define OFF_K0  184320       // k0s[28][128] float
#define OFF_K1  198656       // k1s[28][128] float
#define OFF_XS  212992       // xs[256] float
#define SMEM_TOT 214016

static __device__ __align__(16) unsigned char g_B[CHUNKS * CH_BYTES];

__device__ __forceinline__ uint32_t smem_u32(const void* p) {
    uint32_t a;
    asm("{ .reg .u64 t; cvta.to.shared.u64 t, %1; cvt.u32.u64 %0, t; }" : "=r"(a) : "l"(p));
    return a;
}

#define LDSM4(r0, r1, r2, r3, a)                                               \
    asm volatile("ldmatrix.sync.aligned.m8n8.x4.shared.b16 {%0,%1,%2,%3}, [%4];" \
                 : "=r"(r0), "=r"(r1), "=r"(r2), "=r"(r3) : "r"(a))
#define MMA16816(d, a, b0, b1)                                                 \
    asm volatile("mma.sync.aligned.m16n8k16.row.col.f32.f16.f16.f32 "          \
                 "{%0,%1,%2,%3}, {%4,%5,%6,%7}, {%8,%9}, {%0,%1,%2,%3};"       \
                 : "+f"((d)[0]), "+f"((d)[1]), "+f"((d)[2]), "+f"((d)[3])      \
                 : "r"((a)[0]), "r"((a)[1]), "r"((a)[2]), "r"((a)[3]),         \
                   "r"(b0), "r"(b1))
#define CPASYNC16(dst, src)                                                    \
    asm volatile("cp.async.cg.shared.global [%0], [%1], 16;" :: "r"(dst), "l"(src))

// ---------------- prep: split IF into fp16 hi/lo chunk images ----------------
__global__ void prep_kernel(const float* __restrict__ IF) {
    int idx = blockIdx.x * 256 + threadIdx.x;
    if (idx >= CHUNKS * TF * 56) return;
    const int c  = idx / (TF * 56);
    const int r  = idx - c * (TF * 56);
    const int f  = r / 56;
    const int i  = r - f * 56;
    const int kk = 2 * i;                // local k within chunk, even
    const int pl = kk / PP;              // 0..3
    const int q  = kk - pl * PP;         // even, q+1 <= 27
    const int p  = c * 4 + pl;
    const float v0 = IF[f * (PP * PP) + p * PP + q];
    const float v1 = IF[f * (PP * PP) + p * PP + q + 1];
    __half2 hi = __floats2half2_rn(v0, v1);
    float2 hf  = __half22float2(hi);
    __half2 lo = __floats2half2_rn(v0 - hf.x, v1 - hf.y);
    unsigned char* base = g_B + (size_t)c * CH_BYTES + f * ROWB + kk * 2;
    *reinterpret_cast<uint32_t*>(base)             = *reinterpret_cast<uint32_t*>(&hi);
    *reinterpret_cast<uint32_t*>(base + TEN_BYTES) = *reinterpret_cast<uint32_t*>(&lo);
}

// ---------------- main kernel ----------------
__global__ __launch_bounds__(NTHREADS, 1)
void image_features_hmma_kernel(const float* __restrict__ x,
                                const float* __restrict__ sigma,
                                float* __restrict__ out)
{
    extern __shared__ unsigned char smem[];
    const uint32_t sb = smem_u32(smem);

    const int tid  = threadIdx.x;
    const int lane = tid & 31;
    const int w    = tid >> 5;   // 0..15
    const int wm   = w >> 2;     // 0..3 : rows [wm*32, +32)
    const int wn   = w & 3;      // 0..3 : cols [wn*32, +32)
    const int m0   = blockIdx.x * TM;

    float* xs  = reinterpret_cast<float*>(smem + OFF_XS);
    float* k0s = reinterpret_cast<float*>(smem + OFF_K0);
    float* k1s = reinterpret_cast<float*>(smem + OFF_K1);

    if (tid < 2 * TM) xs[tid] = x[m0 * 2 + tid];
    __syncthreads();

    const float ls  = __expf(sigma[0]);
    const float inv = 0.5f / (ls * ls);

    // exp tables, layout [grid_idx][m]
    for (int idx = tid; idx < PP * TM; idx += NTHREADS) {
        const int g = idx >> 7;
        const int m = idx & 127;
        const float gv = 0.001f + (float)g * (0.998f / 27.0f);
        const float d0 = gv - xs[2 * m + 0];
        const float d1 = gv - xs[2 * m + 1];
        k0s[g * 128 + m] = __expf(-inv * d0 * d0);
        k1s[g * 128 + m] = __expf(-inv * d1 * d1);
    }
    __syncthreads();

    // ---- B prefetch: 61440 B per chunk = 3840 16B-units over 512 threads ----
    auto prefetch = [&](int c, int buf) {
        const uint32_t dst = sb + (buf ? OFF_B1 : OFF_B0);
        const unsigned char* src = g_B + (size_t)c * CH_BYTES;
        #pragma unroll
        for (int j = 0; j < 7; j++) {
            const int u = tid + j * NTHREADS;          // 0..3583
            CPASYNC16(dst + u * 16, src + u * 16);
        }
        {
            const int u = tid + 7 * NTHREADS;          // 3584..4095, keep < 3840
            if (u < 3840) CPASYNC16(dst + u * 16, src + u * 16);
        }
        asm volatile("cp.async.commit_group;" ::: "memory");
    };
    prefetch(0, 0);

    float acc[2][4][4];
    #pragma unroll
    for (int i = 0; i < 2; i++)
        #pragma unroll
        for (int j = 0; j < 4; j++)
            #pragma unroll
            for (int k = 0; k < 4; k++) acc[i][j][k] = 0.0f;

    const int m_ = tid >> 2;     // A-build row (0..127)
    const int pl = tid & 3;      // which p of the 4 in this chunk

    for (int c = 0; c < CHUNKS; c++) {
        if (c + 1 < CHUNKS) prefetch(c + 1, (c + 1) & 1);

        // ---- build A chunk: A[m][pl*28+q] = k0[m, 4c+pl] * k1[m, q] ----
        {
            unsigned char* Ab = smem + OFF_A;
            const int p = 4 * c + pl;
            const float k0v = k0s[p * 128 + m_];
            #pragma unroll
            for (int i2 = 0; i2 < 14; i2++) {
                const int q = 2 * i2;
                const float pr0 = k0v * k1s[q * 128 + m_];
                const float pr1 = k0v * k1s[(q + 1) * 128 + m_];
                __half2 hi = __floats2half2_rn(pr0, pr1);
                float2 hf  = __half22float2(hi);
                __half2 lo = __floats2half2_rn(pr0 - hf.x, pr1 - hf.y);
                const int off = m_ * ROWB + (pl * PP + q) * 2;
                *reinterpret_cast<uint32_t*>(Ab + off) =
                    *reinterpret_cast<uint32_t*>(&hi);
                *reinterpret_cast<uint32_t*>(Ab + TEN_BYTES + off) =
                    *reinterpret_cast<uint32_t*>(&lo);
            }
        }

        if (c + 1 < CHUNKS) asm volatile("cp.async.wait_group %0;" :: "n"(1) : "memory");
        else                asm volatile("cp.async.wait_group %0;" :: "n"(0) : "memory");
        __syncthreads();

        const uint32_t sAh = sb + OFF_A;
        const uint32_t sB  = sb + ((c & 1) ? OFF_B1 : OFF_B0);

        const uint32_t aoff = (lane & 15) * ROWB + (((lane >> 4) << 3) * 2);

        for (int s = 0; s < KSTEP; s++) {
            const uint32_t kboff = s * 32;   // s*16 halfs * 2B

            uint32_t ah[2][4], al[2][4];
            #pragma unroll
            for (int i = 0; i < 2; i++) {
                const uint32_t aa = sAh + (wm * 32 + i * 16) * ROWB + aoff + kboff;
                LDSM4(ah[i][0], ah[i][1], ah[i][2], ah[i][3], aa);
                LDSM4(al[i][0], al[i][1], al[i][2], al[i][3], aa + TEN_BYTES);
            }

            uint32_t bh[2][4], bl[2][4];
            #pragma unroll
            for (int g = 0; g < 2; g++) {
                const uint32_t ba = sB + (wn * 32 + g * 16) * ROWB + aoff + kboff;
                LDSM4(bh[g][0], bh[g][1], bh[g][2], bh[g][3], ba);
                LDSM4(bl[g][0], bl[g][1], bl[g][2], bl[g][3], ba + TEN_BYTES);
            }

            #pragma unroll
            for (int i = 0; i < 2; i++)
                #pragma unroll
                for (int j = 0; j < 4; j++) {
                    const int jg = j >> 1, par = j & 1;
                    MMA16816(acc[i][j], ah[i], bh[jg][par], bh[jg][par + 2]);
                    MMA16816(acc[i][j], al[i], bh[jg][par], bh[jg][par + 2]);
                    MMA16816(acc[i][j], ah[i], bl[jg][par], bl[jg][par + 2]);
                }
        }
        __syncthreads();   // before next chunk's A-build overwrites A
    }

    // ---- epilogue: direct STG, float2 per acc-pair ----
    float* op = out + (size_t)(m0 + wm * 32) * TF + wn * 32;
    #pragma unroll
    for (int i = 0; i < 2; i++) {
        const int row = i * 16 + (lane >> 2);
        #pragma unroll
        for (int j = 0; j < 4; j++) {
            const int col = j * 8 + 2 * (lane & 3);
            float2 v0 = make_float2(acc[i][j][0], acc[i][j][1]);
            float2 v1 = make_float2(acc[i][j][2], acc[i][j][3]);
            *reinterpret_cast<float2*>(op + (size_t)row * TF + col)       = v0;
            *reinterpret_cast<float2*>(op + (size_t)(row + 8) * TF + col) = v1;
        }
    }
}

extern "C" void kernel_launch(void* const* d_in, const int* in_sizes, int n_in,
                              void* d_out, int out_size)
{
    const float* x     = (const float*)d_in[0];   // [B, N, 2]
    const float* sigma = (const float*)d_in[1];   // [1]
    const float* IF    = (const float*)d_in[2];   // [F, P, P]
    float* out         = (float*)d_out;           // [B*N, F]

    const int npoints = in_sizes[0] / 2;
    const int nblocks = npoints / TM;             // 1024

    cudaFuncSetAttribute(image_features_hmma_kernel,
                         cudaFuncAttributeMaxDynamicSharedMemorySize, SMEM_TOT);

    const int prep_n = CHUNKS * TF * 56;
    prep_kernel<<<(prep_n + 255) / 256, 256>>>(IF);
    image_features_hmma_kernel<<<nblocks, NTHREADS, SMEM_TOT>>>(x, sigma, out);
}

// round 6
// speedup vs baseline: 3.2838x; 1.3600x over previous
#include <cuda_runtime.h>
#include <cuda_fp16.h>
#include <cstdint>

// feats[n,f] = sum_{pq} W[n,pq] * IF[f,pq],  W[n, p*28+q] = k0[n,p]*k1[n,q]
// mma.sync m16n8k16 f16->f32 GEMM, 2-pass hi/lo split on A only:
//   D = Ah*Bh + Al*Bh      (B fp16-rounded; residual rel err ~3.7e-4)
// K = 784 = 7 chunks x 112 (7 k16 steps). A hi/lo double-buffered, built on
// the fly; B (fp16 hi only) double-buffered via cp.async. One barrier/chunk:
//   iter c: wait B(c); sync; prefetch B(c+1); build A(c+1); MMA(c)

#define PP 28
#define CHUNKS 7
#define KSTEP 7
#define TM 128
#define TF 128
#define NTHREADS 512
#define ROWB 240             // smem row stride bytes (odd 16B units -> conflict-free)
#define TEN_BYTES 30720      // one tensor: 128 rows * 240B
#define CH_BYTES 30720       // B chunk (hi only)

// smem offsets (bytes)
#define OFF_A0  0            // A buf0: hi [0,30720) lo [30720,61440)
#define OFF_A1  61440        // A buf1
#define OFF_B0  122880       // B hi, buf0
#define OFF_B1  153600       // B hi, buf1
#define OFF_K0  184320       // k0s[28][128] float
#define OFF_K1  198656       // k1s[28][128] float
#define OFF_XS  212992       // xs[256] float
#define SMEM_TOT 214016

static __device__ __align__(16) unsigned char g_B[CHUNKS * CH_BYTES];

__device__ __forceinline__ uint32_t smem_u32(const void* p) {
    uint32_t a;
    asm("{ .reg .u64 t; cvta.to.shared.u64 t, %1; cvt.u32.u64 %0, t; }" : "=r"(a) : "l"(p));
    return a;
}

#define LDSM4(r0, r1, r2, r3, a)                                               \
    asm volatile("ldmatrix.sync.aligned.m8n8.x4.shared.b16 {%0,%1,%2,%3}, [%4];" \
                 : "=r"(r0), "=r"(r1), "=r"(r2), "=r"(r3) : "r"(a))
#define MMA16816(d, a, b0, b1)                                                 \
    asm volatile("mma.sync.aligned.m16n8k16.row.col.f32.f16.f16.f32 "          \
                 "{%0,%1,%2,%3}, {%4,%5,%6,%7}, {%8,%9}, {%0,%1,%2,%3};"       \
                 : "+f"((d)[0]), "+f"((d)[1]), "+f"((d)[2]), "+f"((d)[3])      \
                 : "r"((a)[0]), "r"((a)[1]), "r"((a)[2]), "r"((a)[3]),         \
                   "r"(b0), "r"(b1))
#define CPASYNC16(dst, src)                                                    \
    asm volatile("cp.async.cg.shared.global [%0], [%1], 16;" :: "r"(dst), "l"(src))

// ---------------- prep: fp16 B chunk images (hi only) ----------------
__global__ void prep_kernel(const float* __restrict__ IF) {
    int idx = blockIdx.x * 256 + threadIdx.x;
    if (idx >= CHUNKS * TF * 56) return;
    const int c  = idx / (TF * 56);
    const int r  = idx - c * (TF * 56);
    const int f  = r / 56;
    const int i  = r - f * 56;
    const int kk = 2 * i;                // local k within chunk, even
    const int pl = kk / PP;              // 0..3
    const int q  = kk - pl * PP;
    const int p  = c * 4 + pl;
    const float v0 = IF[f * (PP * PP) + p * PP + q];
    const float v1 = IF[f * (PP * PP) + p * PP + q + 1];
    __half2 hi = __floats2half2_rn(v0, v1);
    *reinterpret_cast<uint32_t*>(g_B + (size_t)c * CH_BYTES + f * ROWB + kk * 2) =
        *reinterpret_cast<uint32_t*>(&hi);
}

// ---------------- main kernel ----------------
__global__ __launch_bounds__(NTHREADS, 1)
void image_features_hmma_kernel(const float* __restrict__ x,
                                const float* __restrict__ sigma,
                                float* __restrict__ out)
{
    extern __shared__ unsigned char smem[];
    const uint32_t sb = smem_u32(smem);

    const int tid  = threadIdx.x;
    const int lane = tid & 31;
    const int w    = tid >> 5;   // 0..15
    const int wm   = w >> 2;     // 0..3 : rows [wm*32, +32)
    const int wn   = w & 3;      // 0..3 : cols [wn*32, +32)
    const int m0   = blockIdx.x * TM;

    float* xs  = reinterpret_cast<float*>(smem + OFF_XS);
    float* k0s = reinterpret_cast<float*>(smem + OFF_K0);
    float* k1s = reinterpret_cast<float*>(smem + OFF_K1);

    if (tid < 2 * TM) xs[tid] = x[m0 * 2 + tid];

    // ---- B prefetch: 30720 B = 1920 16B-units over 512 threads ----
    auto prefetch = [&](int c, int buf) {
        const uint32_t dst = sb + (buf ? OFF_B1 : OFF_B0);
        const unsigned char* src = g_B + (size_t)c * CH_BYTES;
        #pragma unroll
        for (int j = 0; j < 3; j++) {
            const int u = tid + j * NTHREADS;
            CPASYNC16(dst + u * 16, src + u * 16);
        }
        {
            const int u = tid + 3 * NTHREADS;
            if (u < 1920) CPASYNC16(dst + u * 16, src + u * 16);
        }
        asm volatile("cp.async.commit_group;" ::: "memory");
    };
    prefetch(0, 0);
    __syncthreads();   // xs visible

    const float ls  = __expf(sigma[0]);
    const float inv = 0.5f / (ls * ls);

    // exp tables, layout [grid_idx][m]
    for (int idx = tid; idx < PP * TM; idx += NTHREADS) {
        const int g = idx >> 7;
        const int m = idx & 127;
        const float gv = 0.001f + (float)g * (0.998f / 27.0f);
        const float d0 = gv - xs[2 * m + 0];
        const float d1 = gv - xs[2 * m + 1];
        k0s[g * 128 + m] = __expf(-inv * d0 * d0);
        k1s[g * 128 + m] = __expf(-inv * d1 * d1);
    }
    __syncthreads();   // tables visible

    const int m_ = tid >> 2;     // A-build row (0..127)
    const int pl = tid & 3;      // which p of the 4 in a chunk

    // ---- build A chunk c into buffer (c&1): A[m][pl*28+q] = k0[m,4c+pl]*k1[m,q]
    auto buildA = [&](int c) {
        unsigned char* Ab = smem + (c & 1 ? OFF_A1 : OFF_A0);
        const int p = 4 * c + pl;
        const float k0v = k0s[p * 128 + m_];
        #pragma unroll
        for (int i2 = 0; i2 < 14; i2++) {
            const int q = 2 * i2;
            const float pr0 = k0v * k1s[q * 128 + m_];
            const float pr1 = k0v * k1s[(q + 1) * 128 + m_];
            __half2 hi = __floats2half2_rn(pr0, pr1);
            float2 hf  = __half22float2(hi);
            __half2 lo = __floats2half2_rn(pr0 - hf.x, pr1 - hf.y);
            const int off = m_ * ROWB + (pl * PP + q) * 2;
            *reinterpret_cast<uint32_t*>(Ab + off) =
                *reinterpret_cast<uint32_t*>(&hi);
            *reinterpret_cast<uint32_t*>(Ab + TEN_BYTES + off) =
                *reinterpret_cast<uint32_t*>(&lo);
        }
    };
    buildA(0);

    float acc[2][4][4];
    #pragma unroll
    for (int i = 0; i < 2; i++)
        #pragma unroll
        for (int j = 0; j < 4; j++)
            #pragma unroll
            for (int k = 0; k < 4; k++) acc[i][j][k] = 0.0f;

    const uint32_t aoff = (lane & 15) * ROWB + (((lane >> 4) << 3) * 2);

    for (int c = 0; c < CHUNKS; c++) {
        // wait for B(c); B(c+1) not yet committed so wait-all is exactly B(c)
        asm volatile("cp.async.wait_group 0;" ::: "memory");
        __syncthreads();   // publishes A(c) build + B(c); fences MMA(c-1) readers

        if (c + 1 < CHUNKS) {
            prefetch(c + 1, (c + 1) & 1);
            buildA(c + 1);
        }

        const uint32_t sA = sb + ((c & 1) ? OFF_A1 : OFF_A0);
        const uint32_t sB = sb + ((c & 1) ? OFF_B1 : OFF_B0);

        for (int s = 0; s < KSTEP; s++) {
            const uint32_t kboff = s * 32;

            uint32_t ah[2][4], al[2][4];
            #pragma unroll
            for (int i = 0; i < 2; i++) {
                const uint32_t aa = sA + (wm * 32 + i * 16) * ROWB + aoff + kboff;
                LDSM4(ah[i][0], ah[i][1], ah[i][2], ah[i][3], aa);
                LDSM4(al[i][0], al[i][1], al[i][2], al[i][3], aa + TEN_BYTES);
            }

            uint32_t bh[2][4];
            #pragma unroll
            for (int g = 0; g < 2; g++) {
                const uint32_t ba = sB + (wn * 32 + g * 16) * ROWB + aoff + kboff;
                LDSM4(bh[g][0], bh[g][1], bh[g][2], bh[g][3], ba);
            }

            #pragma unroll
            for (int i = 0; i < 2; i++)
                #pragma unroll
                for (int j = 0; j < 4; j++) {
                    const int jg = j >> 1, par = j & 1;
                    MMA16816(acc[i][j], ah[i], bh[jg][par], bh[jg][par + 2]);
                    MMA16816(acc[i][j], al[i], bh[jg][par], bh[jg][par + 2]);
                }
        }
    }

    // ---- epilogue: direct STG, float2 per acc-pair ----
    float* op = out + (size_t)(m0 + wm * 32) * TF + wn * 32;
    #pragma unroll
    for (int i = 0; i < 2; i++) {
        const int row = i * 16 + (lane >> 2);
        #pragma unroll
        for (int j = 0; j < 4; j++) {
            const int col = j * 8 + 2 * (lane & 3);
            float2 v0 = make_float2(acc[i][j][0], acc[i][j][1]);
            float2 v1 = make_float2(acc[i][j][2], acc[i][j][3]);
            *reinterpret_cast<float2*>(op + (size_t)row * TF + col)       = v0;
            *reinterpret_cast<float2*>(op + (size_t)(row + 8) * TF + col) = v1;
        }
    }
}

extern "C" void kernel_launch(void* const* d_in, const int* in_sizes, int n_in,
                              void* d_out, int out_size)
{
    const float* x     = (const float*)d_in[0];   // [B, N, 2]
    const float* sigma = (const float*)d_in[1];   // [1]
    const float* IF    = (const float*)d_in[2];   // [F, P, P]
    float* out         = (float*)d_out;           // [B*N, F]

    const int npoints = in_sizes[0] / 2;
    const int nblocks = npoints / TM;             // 1024

    cudaFuncSetAttribute(image_features_hmma_kernel,
                         cudaFuncAttributeMaxDynamicSharedMemorySize, SMEM_TOT);

    const int prep_n = CHUNKS * TF * 56;
    prep_kernel<<<(prep_n + 255) / 256, 256>>>(IF);
    image_features_hmma_kernel<<<nblocks, NTHREADS, SMEM_TOT>>>(x, sigma, out);
}

// round 7
// speedup vs baseline: 5.2138x; 1.5877x over previous
#include <cuda_runtime.h>
#include <cuda_fp16.h>
#include <cstdint>

// feats[n,f] = sum_{pq} W[n,pq] * IF[f,pq],  W[n, p*28+q] = k0[n,p]*k1[n,q]
// mma.sync m16n8k16 f16->f32 GEMM, single-pass fp16 (A and B both fp16-rounded,
// fp32 accumulate). Symmetric rounding error analysis + measured B-only error
// (2.07e-4) => total ~2.9e-4, safely under the 1e-3 gate.
// K = 784 = 7 chunks x 112 (7 k16 steps). A double-buffered, built on the fly
// from exp tables; B double-buffered via cp.async. One barrier per chunk:
//   iter c: wait B(c); sync; prefetch B(c+1); build A(c+1); MMA(c)

#define PP 28
#define CHUNKS 7
#define KSTEP 7
#define TM 128
#define TF 128
#define NTHREADS 512
#define ROWB 240             // smem row stride bytes (odd 16B units -> conflict-free)
#define TEN_BYTES 30720      // one tensor: 128 rows * 240B
#define CH_BYTES 30720       // B chunk (fp16)

// smem offsets (bytes)
#define OFF_A0  0            // A buf0 (fp16)
#define OFF_A1  30720        // A buf1
#define OFF_B0  61440        // B buf0
#define OFF_B1  92160        // B buf1
#define OFF_K0  122880       // k0s[28][128] float
#define OFF_K1  137216       // k1s[28][128] float
#define OFF_XS  151552       // xs[256] float
#define SMEM_TOT 152576

static __device__ __align__(16) unsigned char g_B[CHUNKS * CH_BYTES];

__device__ __forceinline__ uint32_t smem_u32(const void* p) {
    uint32_t a;
    asm("{ .reg .u64 t; cvta.to.shared.u64 t, %1; cvt.u32.u64 %0, t; }" : "=r"(a) : "l"(p));
    return a;
}

#define LDSM4(r0, r1, r2, r3, a)                                               \
    asm volatile("ldmatrix.sync.aligned.m8n8.x4.shared.b16 {%0,%1,%2,%3}, [%4];" \
                 : "=r"(r0), "=r"(r1), "=r"(r2), "=r"(r3) : "r"(a))
#define MMA16816(d, a, b0, b1)                                                 \
    asm volatile("mma.sync.aligned.m16n8k16.row.col.f32.f16.f16.f32 "          \
                 "{%0,%1,%2,%3}, {%4,%5,%6,%7}, {%8,%9}, {%0,%1,%2,%3};"       \
                 : "+f"((d)[0]), "+f"((d)[1]), "+f"((d)[2]), "+f"((d)[3])      \
                 : "r"((a)[0]), "r"((a)[1]), "r"((a)[2]), "r"((a)[3]),         \
                   "r"(b0), "r"(b1))
#define CPASYNC16(dst, src)                                                    \
    asm volatile("cp.async.cg.shared.global [%0], [%1], 16;" :: "r"(dst), "l"(src))

// ---------------- prep: fp16 B chunk images ----------------
__global__ void prep_kernel(const float* __restrict__ IF) {
    int idx = blockIdx.x * 256 + threadIdx.x;
    if (idx >= CHUNKS * TF * 56) return;
    const int c  = idx / (TF * 56);
    const int r  = idx - c * (TF * 56);
    const int f  = r / 56;
    const int i  = r - f * 56;
    const int kk = 2 * i;                // local k within chunk, even
    const int pl = kk / PP;              // 0..3
    const int q  = kk - pl * PP;
    const int p  = c * 4 + pl;
    const float v0 = IF[f * (PP * PP) + p * PP + q];
    const float v1 = IF[f * (PP * PP) + p * PP + q + 1];
    __half2 hi = __floats2half2_rn(v0, v1);
    *reinterpret_cast<uint32_t*>(g_B + (size_t)c * CH_BYTES + f * ROWB + kk * 2) =
        *reinterpret_cast<uint32_t*>(&hi);
}

// ---------------- main kernel ----------------
__global__ __launch_bounds__(NTHREADS, 1)
void image_features_hmma_kernel(const float* __restrict__ x,
                                const float* __restrict__ sigma,
                                float* __restrict__ out)
{
    extern __shared__ unsigned char smem[];
    const uint32_t sb = smem_u32(smem);

    const int tid  = threadIdx.x;
    const int lane = tid & 31;
    const int w    = tid >> 5;   // 0..15
    const int wm   = w >> 2;     // 0..3 : rows [wm*32, +32)
    const int wn   = w & 3;      // 0..3 : cols [wn*32, +32)
    const int m0   = blockIdx.x * TM;

    float* xs  = reinterpret_cast<float*>(smem + OFF_XS);
    float* k0s = reinterpret_cast<float*>(smem + OFF_K0);
    float* k1s = reinterpret_cast<float*>(smem + OFF_K1);

    if (tid < 2 * TM) xs[tid] = x[m0 * 2 + tid];

    // ---- B prefetch: 30720 B = 1920 16B-units over 512 threads ----
    auto prefetch = [&](int c, int buf) {
        const uint32_t dst = sb + (buf ? OFF_B1 : OFF_B0);
        const unsigned char* src = g_B + (size_t)c * CH_BYTES;
        #pragma unroll
        for (int j = 0; j < 3; j++) {
            const int u = tid + j * NTHREADS;
            CPASYNC16(dst + u * 16, src + u * 16);
        }
        {
            const int u = tid + 3 * NTHREADS;
            if (u < 1920) CPASYNC16(dst + u * 16, src + u * 16);
        }
        asm volatile("cp.async.commit_group;" ::: "memory");
    };
    prefetch(0, 0);
    __syncthreads();   // xs visible

    const float ls  = __expf(sigma[0]);
    const float inv = 0.5f / (ls * ls);

    // exp tables, layout [grid_idx][m]
    for (int idx = tid; idx < PP * TM; idx += NTHREADS) {
        const int g = idx >> 7;
        const int m = idx & 127;
        const float gv = 0.001f + (float)g * (0.998f / 27.0f);
        const float d0 = gv - xs[2 * m + 0];
        const float d1 = gv - xs[2 * m + 1];
        k0s[g * 128 + m] = __expf(-inv * d0 * d0);
        k1s[g * 128 + m] = __expf(-inv * d1 * d1);
    }
    __syncthreads();   // tables visible

    const int m_ = tid >> 2;     // A-build row (0..127)
    const int pl = tid & 3;      // which p of the 4 in a chunk

    // ---- build A chunk c into buffer (c&1): A[m][pl*28+q] = k0[m,4c+pl]*k1[m,q]
    auto buildA = [&](int c) {
        unsigned char* Ab = smem + (c & 1 ? OFF_A1 : OFF_A0);
        const int p = 4 * c + pl;
        const float k0v = k0s[p * 128 + m_];
        #pragma unroll
        for (int i2 = 0; i2 < 14; i2++) {
            const int q = 2 * i2;
            const float pr0 = k0v * k1s[q * 128 + m_];
            const float pr1 = k0v * k1s[(q + 1) * 128 + m_];
            __half2 hi = __floats2half2_rn(pr0, pr1);
            *reinterpret_cast<uint32_t*>(Ab + m_ * ROWB + (pl * PP + q) * 2) =
                *reinterpret_cast<uint32_t*>(&hi);
        }
    };
    buildA(0);

    float acc[2][4][4];
    #pragma unroll
    for (int i = 0; i < 2; i++)
        #pragma unroll
        for (int j = 0; j < 4; j++)
            #pragma unroll
            for (int k = 0; k < 4; k++) acc[i][j][k] = 0.0f;

    const uint32_t aoff = (lane & 15) * ROWB + (((lane >> 4) << 3) * 2);

    for (int c = 0; c < CHUNKS; c++) {
        // wait for B(c); B(c+1) not yet committed so wait-all is exactly B(c)
        asm volatile("cp.async.wait_group 0;" ::: "memory");
        __syncthreads();   // publishes A(c) build + B(c); fences MMA(c-1) readers

        if (c + 1 < CHUNKS) {
            prefetch(c + 1, (c + 1) & 1);
            buildA(c + 1);
        }

        const uint32_t sA = sb + ((c & 1) ? OFF_A1 : OFF_A0);
        const uint32_t sB = sb + ((c & 1) ? OFF_B1 : OFF_B0);

        for (int s = 0; s < KSTEP; s++) {
            const uint32_t kboff = s * 32;

            uint32_t ah[2][4];
            #pragma unroll
            for (int i = 0; i < 2; i++) {
                const uint32_t aa = sA + (wm * 32 + i * 16) * ROWB + aoff + kboff;
                LDSM4(ah[i][0], ah[i][1], ah[i][2], ah[i][3], aa);
            }

            uint32_t bh[2][4];
            #pragma unroll
            for (int g = 0; g < 2; g++) {
                const uint32_t ba = sB + (wn * 32 + g * 16) * ROWB + aoff + kboff;
                LDSM4(bh[g][0], bh[g][1], bh[g][2], bh[g][3], ba);
            }

            #pragma unroll
            for (int i = 0; i < 2; i++)
                #pragma unroll
                for (int j = 0; j < 4; j++) {
                    const int jg = j >> 1, par = j & 1;
                    MMA16816(acc[i][j], ah[i], bh[jg][par], bh[jg][par + 2]);
                }
        }
    }

    // ---- epilogue: direct STG, float2 per acc-pair ----
    float* op = out + (size_t)(m0 + wm * 32) * TF + wn * 32;
    #pragma unroll
    for (int i = 0; i < 2; i++) {
        const int row = i * 16 + (lane >> 2);
        #pragma unroll
        for (int j = 0; j < 4; j++) {
            const int col = j * 8 + 2 * (lane & 3);
            float2 v0 = make_float2(acc[i][j][0], acc[i][j][1]);
            float2 v1 = make_float2(acc[i][j][2], acc[i][j][3]);
            *reinterpret_cast<float2*>(op + (size_t)row * TF + col)       = v0;
            *reinterpret_cast<float2*>(op + (size_t)(row + 8) * TF + col) = v1;
        }
    }
}

extern "C" void kernel_launch(void* const* d_in, const int* in_sizes, int n_in,
                              void* d_out, int out_size)
{
    const float* x     = (const float*)d_in[0];   // [B, N, 2]
    const float* sigma = (const float*)d_in[1];   // [1]
    const float* IF    = (const float*)d_in[2];   // [F, P, P]
    float* out         = (float*)d_out;           // [B*N, F]

    const int npoints = in_sizes[0] / 2;
    const int nblocks = npoints / TM;             // 1024

    cudaFuncSetAttribute(image_features_hmma_kernel,
                         cudaFuncAttributeMaxDynamicSharedMemorySize, SMEM_TOT);

    const int prep_n = CHUNKS * TF * 56;
    prep_kernel<<<(prep_n + 255) / 256, 256>>>(IF);
    image_features_hmma_kernel<<<nblocks, NTHREADS, SMEM_TOT>>>(x, sigma, out);
}